// round 16
// baseline (speedup 1.0000x reference)
#include <cuda_runtime.h>
#include <cstdint>
#include <math.h>

// Problem dims
#define NB   64
#define SEQ  512
#define IMG  3200
#define FC   64
#define HID  256
#define G4   1024

// Output layout (floats): [logprobs 64*512*2 | output_feats 64*512*256 | selected 64*256]
#define OFF_LP  0
#define OFF_OF  (NB*SEQ*2)
#define OFF_SEL (OFF_OF + NB*SEQ*HID)

// ---------------- scratch ----------------
__device__ float g_emb[NB * FC];
__device__ float g_fuse[NB * SEQ * FC];

// ---------------- helpers ----------------
__device__ __forceinline__ float2 ffma2(float2 a, float2 b, float2 c) {
    unsigned long long ua = *reinterpret_cast<unsigned long long*>(&a);
    unsigned long long ub = *reinterpret_cast<unsigned long long*>(&b);
    unsigned long long uc = *reinterpret_cast<unsigned long long*>(&c);
    unsigned long long ud;
    asm("fma.rn.f32x2 %0, %1, %2, %3;" : "=l"(ud) : "l"(ua), "l"(ub), "l"(uc));
    return *reinterpret_cast<float2*>(&ud);
}

__device__ __forceinline__ uint32_t smem_u32(const void* p) {
    uint32_t a;
    asm("{ .reg .u64 t; cvta.to.shared.u64 t, %1; cvt.u32.u64 %0, t; }" : "=r"(a) : "l"(p));
    return a;
}

// HW tanh (MUFU.TANH, sm_75+)
__device__ __forceinline__ float tanh_hw(float x) {
    float y;
    asm("tanh.approx.f32 %0, %1;" : "=f"(y) : "f"(x));
    return y;
}
__device__ __forceinline__ float sigm(float x)  { return fmaf(0.5f, tanh_hw(0.5f * x), 0.5f); }
__device__ __forceinline__ float tanh_(float x) { return tanh_hw(x); }

__device__ __forceinline__ void mbar_init(uint32_t a, uint32_t c) {
    asm volatile("mbarrier.init.shared.b64 [%0], %1;" :: "r"(a), "r"(c) : "memory");
}
__device__ __forceinline__ void mbar_expect_tx(uint32_t a, uint32_t tx) {
    asm volatile("mbarrier.arrive.expect_tx.shared.b64 _, [%0], %1;" :: "r"(a), "r"(tx) : "memory");
}
__device__ __forceinline__ void mbar_wait(uint32_t a, uint32_t phase) {
    asm volatile(
        "{\n\t"
        ".reg .pred P;\n\t"
        "WL_%=:\n\t"
        "mbarrier.try_wait.parity.acquire.cta.shared::cta.b64 P, [%0], %1, 0x989680;\n\t"
        "@P bra WD_%=;\n\t"
        "bra WL_%=;\n\t"
        "WD_%=:\n\t"
        "}" :: "r"(a), "r"(phase) : "memory");
}
__device__ __forceinline__ uint32_t mapa_u32(uint32_t a, uint32_t r) {
    uint32_t ra;
    asm("mapa.shared::cluster.u32 %0, %1, %2;" : "=r"(ra) : "r"(a), "r"(r));
    return ra;
}
__device__ __forceinline__ void st_async_f32x2(uint32_t dst, float a, float b, uint32_t rbar) {
    unsigned long long v;
    asm("mov.b64 %0, {%1, %2};" : "=l"(v) : "r"(__float_as_uint(a)), "r"(__float_as_uint(b)));
    asm volatile("st.async.shared::cluster.mbarrier::complete_tx::bytes.b64 [%0], %1, [%2];"
                 :: "r"(dst), "l"(v), "r"(rbar) : "memory");
}

// ---------------- kernel 1: emb ----------------
__global__ void emb_kernel(const float* __restrict__ phr,
                           const float* __restrict__ Wp,
                           const float* __restrict__ bp) {
    __shared__ float ps[304];
    int b = blockIdx.x, tid = threadIdx.x;
    for (int i = tid; i < 300; i += 64) ps[i] = phr[b * 300 + i];
    __syncthreads();
    float acc = bp[tid];
#pragma unroll 4
    for (int k = 0; k < 300; k++) acc += ps[k] * Wp[k * 64 + tid];
    g_emb[b * 64 + tid] = fmaxf(acc, 0.0f);
}

// ---------------- kernel 2: fuse ----------------
__global__ __launch_bounds__(256) void fuse_kernel(const float* __restrict__ img,
                                                   const float* __restrict__ Wc,
                                                   const float* __restrict__ bc) {
    __shared__ float As[2][16][132];
    __shared__ float Bs[2][16][64];
    __shared__ float es[64];

    const int tid = threadIdx.x;
    const int tx = tid & 15, ty = tid >> 4;
    const int row0 = blockIdx.x * 128;
    const int batch = row0 >> 9;

    if (tid < 64) es[tid] = g_emb[batch * 64 + tid];

    float bcr[4];
#pragma unroll
    for (int c = 0; c < 4; c++) bcr[c] = bc[tx * 4 + c];

    float2 acc[4][4];
#pragma unroll
    for (int mp = 0; mp < 4; mp++)
#pragma unroll
        for (int c = 0; c < 4; c++) acc[mp][c] = make_float2(0.f, 0.f);

    auto loadA = [&](int s, int kk) {
#pragma unroll
        for (int i = 0; i < 2; i++) {
            int id = tid * 2 + i;
            int m = id >> 2, q = id & 3;
            float4 v = *reinterpret_cast<const float4*>(img + (size_t)(row0 + m) * IMG + kk + q * 4);
            As[s][q * 4 + 0][m] = v.x;
            As[s][q * 4 + 1][m] = v.y;
            As[s][q * 4 + 2][m] = v.z;
            As[s][q * 4 + 3][m] = v.w;
        }
    };
    auto loadB = [&](int s, int kk) {
        int k = tid >> 4, q = tid & 15;
        *reinterpret_cast<float4*>(&Bs[s][k][q * 4]) =
            *reinterpret_cast<const float4*>(Wc + (size_t)(kk + k) * 64 + q * 4);
    };

    loadA(0, 0);
    loadB(0, 0);
    __syncthreads();

    for (int ch = 0; ch < 200; ch++) {
        int s = ch & 1;
        if (ch + 1 < 200) { loadA(s ^ 1, (ch + 1) * 16); loadB(s ^ 1, (ch + 1) * 16); }
#pragma unroll
        for (int k = 0; k < 16; k++) {
            float4 b4 = *reinterpret_cast<const float4*>(&Bs[s][k][tx * 4]);
            float4 a0 = *reinterpret_cast<const float4*>(&As[s][k][ty * 8]);
            float4 a1 = *reinterpret_cast<const float4*>(&As[s][k][ty * 8 + 4]);
            float2 aa[4] = { {a0.x, a0.y}, {a0.z, a0.w}, {a1.x, a1.y}, {a1.z, a1.w} };
            float  bb[4] = { b4.x, b4.y, b4.z, b4.w };
#pragma unroll
            for (int c = 0; c < 4; c++) {
                float2 bv = make_float2(bb[c], bb[c]);
#pragma unroll
                for (int mp = 0; mp < 4; mp++) acc[mp][c] = ffma2(aa[mp], bv, acc[mp][c]);
            }
        }
        __syncthreads();
    }

    float sc[4];
#pragma unroll
    for (int c = 0; c < 4; c++) sc[c] = es[tx * 4 + c];

#pragma unroll
    for (int mp = 0; mp < 4; mp++) {
        float4 r0v, r1v;
        r0v.x = fmaxf(acc[mp][0].x + bcr[0], 0.f) * sc[0];
        r0v.y = fmaxf(acc[mp][1].x + bcr[1], 0.f) * sc[1];
        r0v.z = fmaxf(acc[mp][2].x + bcr[2], 0.f) * sc[2];
        r0v.w = fmaxf(acc[mp][3].x + bcr[3], 0.f) * sc[3];
        r1v.x = fmaxf(acc[mp][0].y + bcr[0], 0.f) * sc[0];
        r1v.y = fmaxf(acc[mp][1].y + bcr[1], 0.f) * sc[1];
        r1v.z = fmaxf(acc[mp][2].y + bcr[2], 0.f) * sc[2];
        r1v.w = fmaxf(acc[mp][3].y + bcr[3], 0.f) * sc[3];
        int r = row0 + ty * 8 + mp * 2;
        *reinterpret_cast<float4*>(g_fuse + (size_t)r * 64 + tx * 4)       = r0v;
        *reinterpret_cast<float4*>(g_fuse + (size_t)(r + 1) * 64 + tx * 4) = r1v;
    }
}

// ---------------- kernel 3: LSTM (R15 exact; b64 pair-sends halve msg count) ----------------
#define PADQ 68
#define HBUF_BYTES (4 * 4 * PADQ * 4)   // one h buffer: 4352 B

__global__ void __cluster_dims__(8, 1, 1) __launch_bounds__(512, 1)
lstm_kernel(const float* __restrict__ Whh,
            const float* __restrict__ Wih,
            const float* __restrict__ bih,
            const float* __restrict__ bhh,
            float* __restrict__ of) {
    __shared__ __align__(16) float hbuf[2][4][4][PADQ];   // [buf][b][q][64(+4)]
    __shared__ __align__(16) float xs[2][4][PADQ];        // [buf][b][64(+4)]
    __shared__ __align__(16) float gsm[128][4];           // [gate-local][b]
    __shared__ __align__(16) float Wi_s[64 * 128];        // W_ih staging (init only)
    __shared__ __align__(8)  unsigned long long bars[2];

    const int tid  = threadIdx.x;
    const int warp = tid >> 5, lane = tid & 31;
    const int gl = lane & 7, q = lane >> 3;
    const int g  = warp * 8 + gl;          // gate slot 0..127
    const int rank   = blockIdx.x & 7;
    const int batch0 = (blockIdx.x >> 3) * 4;
    const int col = ((g >> 5) << 8) + (rank << 5) + (g & 31);  // column in [0,1024)

    // ---- stage W_ih slice coalesced (init only) ----
    for (int i = tid; i < 8192; i += 512) {
        int k = i >> 7, c = i & 127;
        int cg = ((c >> 5) << 8) + (rank << 5) + (c & 31);
        Wi_s[k * 128 + c] = Wih[(size_t)k * G4 + cg];
    }

    // ---- W_hh registers: k in [q*64, q*64+64), packed as 32 float2 (exact R2) ----
    float2 Wr[32];
    {
        const float* wp = Whh + (size_t)(q * 64) * G4 + col;
#pragma unroll
        for (int j = 0; j < 32; j++) {
            Wr[j].x = wp[(size_t)(2 * j) * G4];
            Wr[j].y = wp[(size_t)(2 * j + 1) * G4];
        }
    }
    // bias folded into xacc, added once (q==0 lanes only)
    float bg = (q == 0) ? (bih[col] + bhh[col]) : 0.0f;

    const uint32_t bar0 = smem_u32(&bars[0]);
    if (tid == 0) {
        mbar_init(bar0, 1);
        mbar_init(bar0 + 8, 1);
        mbar_expect_tx(bar0, 4096);       // armed for first use (t=2)
        mbar_expect_tx(bar0 + 8, 4096);   // armed for first use (t=1)
    }
    // prefetch x for t=0 (xs[0]) and t=1 (xs[1])
    if (tid < 128) {
        int buf = tid >> 6;               // 0 or 1
        int e = tid & 63;
        int b = e >> 4, j = e & 15;
        *reinterpret_cast<float4*>(&xs[buf][b][j * 4]) =
            *reinterpret_cast<const float4*>(g_fuse + ((size_t)(batch0 + b) * SEQ + buf) * FC + j * 4);
    }
    __syncthreads();

    // ---- W_ih registers: k in [q*16, q*16+16) for gate g ----
    float2 Wir[8];
#pragma unroll
    for (int j = 0; j < 8; j++) {
        int k = q * 16 + 2 * j;
        Wir[j].x = Wi_s[k * 128 + g];
        Wir[j].y = Wi_s[(k + 1) * 128 + g];
    }

    asm volatile("barrier.cluster.arrive.aligned;" ::: "memory");
    asm volatile("barrier.cluster.wait.aligned;"   ::: "memory");

    // producer identity (threads 0..127): batch bb, unit ub (exact R2)
    const int bb = tid >> 5, ub = tid & 31;
    const int kglob = (rank << 5) + ub;
    uint32_t dst_loc0 = 0, barloc = bar0;
    if (tid < 128)
        dst_loc0 = smem_u32(&hbuf[0][bb][kglob >> 6][kglob & 63]);

    // ---- xacc for t=0 (from xs[0]) ----
    float xacc[4];
    {
#pragma unroll
        for (int b = 0; b < 4; b++) {
            const float* xp = &xs[0][b][q * 16];
            float2 a = make_float2(bg * 0.5f, bg * 0.5f);   // a.x + a.y = bg
#pragma unroll
            for (int i = 0; i < 8; i++) {
                float2 x2 = *reinterpret_cast<const float2*>(xp + 2 * i);
                a = ffma2(Wir[i], x2, a);
            }
            xacc[b] = a.x + a.y;
        }
    }

    float creg = 0.0f;
    int ph0 = 0, ph1 = 0;

    for (int t = 0; t < SEQ; t++) {
        const int p = t & 1;
        float val[4];
#pragma unroll
        for (int b = 0; b < 4; b++) val[b] = xacc[b];

        if (t > 0) {
            uint32_t barp = bar0 + p * 8;
            int par = p ? ph1 : ph0;
            mbar_wait(barp, par);
            if (p) ph1 ^= 1; else ph0 ^= 1;
            if (tid == 0) mbar_expect_tx(barp, 4096);   // re-arm for t+2

            // ---- recurrent GEMM (exact R2) ----
#pragma unroll
            for (int b = 0; b < 4; b++) {
                float2 acc = make_float2(0.f, 0.f);
                const float* hp = &hbuf[p][b][q][0];
#pragma unroll
                for (int j = 0; j < 16; j++) {
                    float4 h4 = *reinterpret_cast<const float4*>(hp + j * 4);
                    acc = ffma2(Wr[2 * j],     make_float2(h4.x, h4.y), acc);
                    acc = ffma2(Wr[2 * j + 1], make_float2(h4.z, h4.w), acc);
                }
                val[b] += acc.x + acc.y;
            }
        }

        // reduce across quarters (exact R2)
#pragma unroll
        for (int b = 0; b < 4; b++) {
            val[b] += __shfl_xor_sync(0xffffffffu, val[b], 8);
            val[b] += __shfl_xor_sync(0xffffffffu, val[b], 16);
        }
        if (lane < 8) {
            float4 v = make_float4(val[0], val[1], val[2], val[3]);
            *reinterpret_cast<float4*>(&gsm[warp * 8 + lane][0]) = v;
        }
        __syncthreads();

        if (tid < 128) {
            float gi = gsm[ub][bb];
            float gf = gsm[32 + ub][bb];
            float gg = gsm[64 + ub][bb];
            float go = gsm[96 + ub][bb];
            float tg = tanh_(gg);
            creg = sigm(gf) * creg + sigm(gi) * tg;
            float h = sigm(go) * tanh_(creg);

            // pair units (ub even, ub+1): halve the st.async count via b64
            float ho = __shfl_xor_sync(0xffffffffu, h, 1);
            if (t + 1 < SEQ && (ub & 1) == 0) {
                uint32_t doff = dst_loc0 + (p ^ 1) * HBUF_BYTES;
                uint32_t boff = barloc + (p ^ 1) * 8;
#pragma unroll
                for (int r = 0; r < 8; r++) {
                    uint32_t rd = mapa_u32(doff, r);
                    uint32_t rb = mapa_u32(boff, r);
                    st_async_f32x2(rd, h, ho, rb);
                }
            }
            of[(size_t)(batch0 + bb) * (SEQ * HID) + (size_t)t * HID + (rank << 5) + ub] = h;
        } else if (tid < 192 && t + 2 < SEQ) {
            // prefetch x for t+2 into xs[(t+2)&1] = xs[p]
            int e = tid - 128;
            int b = e >> 4, j = e & 15;
            *reinterpret_cast<float4*>(&xs[p][b][j * 4]) =
                *reinterpret_cast<const float4*>(g_fuse + ((size_t)(batch0 + b) * SEQ + (t + 2)) * FC + j * 4);
        }

        // ---- xacc for t+1 from xs[p^1] (regs-only weights; hidden under act/send) ----
        if (t + 1 < SEQ) {
#pragma unroll
            for (int b = 0; b < 4; b++) {
                const float* xp = &xs[p ^ 1][b][q * 16];
                float2 a = make_float2(bg * 0.5f, bg * 0.5f);
#pragma unroll
                for (int i = 0; i < 8; i++) {
                    float2 x2 = *reinterpret_cast<const float2*>(xp + 2 * i);
                    a = ffma2(Wir[i], x2, a);
                }
                xacc[b] = a.x + a.y;
            }
        }
        // no trailing sync (exact R2)
    }

    asm volatile("barrier.cluster.arrive.aligned;" ::: "memory");
    asm volatile("barrier.cluster.wait.aligned;"   ::: "memory");
}

// ---------------- kernel 4: classifier + log_softmax ----------------
__global__ __launch_bounds__(256) void cls_kernel(const float* __restrict__ of,
                                                  const float* __restrict__ W1,
                                                  const float* __restrict__ b1,
                                                  const float* __restrict__ W2,
                                                  const float* __restrict__ b2,
                                                  float* __restrict__ lp) {
    __shared__ float As[2][16][132];
    __shared__ float Bs[2][16][64];

    const int tid = threadIdx.x;
    const int tx = tid & 15, ty = tid >> 4;
    const int row0 = blockIdx.x * 128;

    float b1r[4], w20[4], w21[4];
#pragma unroll
    for (int c = 0; c < 4; c++) {
        int f = tx * 4 + c;
        b1r[c] = b1[f];
        w20[c] = W2[f * 2 + 0];
        w21[c] = W2[f * 2 + 1];
    }
    const float bb0 = b2[0], bb1 = b2[1];

    float2 acc[4][4];
#pragma unroll
    for (int mp = 0; mp < 4; mp++)
#pragma unroll
        for (int c = 0; c < 4; c++) acc[mp][c] = make_float2(0.f, 0.f);

    auto loadA = [&](int s, int kk) {
#pragma unroll
        for (int i = 0; i < 2; i++) {
            int id = tid * 2 + i;
            int m = id >> 2, q = id & 3;
            float4 v = *reinterpret_cast<const float4*>(of + (size_t)(row0 + m) * HID + kk + q * 4);
            As[s][q * 4 + 0][m] = v.x;
            As[s][q * 4 + 1][m] = v.y;
            As[s][q * 4 + 2][m] = v.z;
            As[s][q * 4 + 3][m] = v.w;
        }
    };
    auto loadB = [&](int s, int kk) {
        int k = tid >> 4, q = tid & 15;
        *reinterpret_cast<float4*>(&Bs[s][k][q * 4]) =
            *reinterpret_cast<const float4*>(W1 + (size_t)(kk + k) * 64 + q * 4);
    };

    loadA(0, 0);
    loadB(0, 0);
    __syncthreads();

    for (int ch = 0; ch < 16; ch++) {
        int s = ch & 1;
        if (ch + 1 < 16) { loadA(s ^ 1, (ch + 1) * 16); loadB(s ^ 1, (ch + 1) * 16); }
#pragma unroll
        for (int k = 0; k < 16; k++) {
            float4 b4 = *reinterpret_cast<const float4*>(&Bs[s][k][tx * 4]);
            float4 a0 = *reinterpret_cast<const float4*>(&As[s][k][ty * 8]);
            float4 a1 = *reinterpret_cast<const float4*>(&As[s][k][ty * 8 + 4]);
            float2 aa[4] = { {a0.x, a0.y}, {a0.z, a0.w}, {a1.x, a1.y}, {a1.z, a1.w} };
            float  bb[4] = { b4.x, b4.y, b4.z, b4.w };
#pragma unroll
            for (int c = 0; c < 4; c++) {
                float2 bv = make_float2(bb[c], bb[c]);
#pragma unroll
                for (int mp = 0; mp < 4; mp++) acc[mp][c] = ffma2(aa[mp], bv, acc[mp][c]);
            }
        }
        __syncthreads();
    }

#pragma unroll
    for (int mp = 0; mp < 4; mp++) {
#pragma unroll
        for (int half = 0; half < 2; half++) {
            float p0 = 0.f, p1 = 0.f;
#pragma unroll
            for (int c = 0; c < 4; c++) {
                float vv = half ? acc[mp][c].y : acc[mp][c].x;
                float hd = fmaxf(vv + b1r[c], 0.f);
                p0 += hd * w20[c];
                p1 += hd * w21[c];
            }
#pragma unroll
            for (int s = 1; s < 16; s <<= 1) {
                p0 += __shfl_xor_sync(0xffffffffu, p0, s);
                p1 += __shfl_xor_sync(0xffffffffu, p1, s);
            }
            if ((tid & 15) == 0) {
                float l0 = p0 + bb0, l1 = p1 + bb1;
                float m = fmaxf(l0, l1);
                float lse = m + logf(expf(l0 - m) + expf(l1 - m));
                int row = row0 + ty * 8 + mp * 2 + half;
                lp[row * 2 + 0] = l0 - lse;
                lp[row * 2 + 1] = l1 - lse;
            }
        }
    }
}

// ---------------- kernel 5: gather selected ----------------
__global__ void sel_kernel(const int* __restrict__ ix, const float* __restrict__ of,
                           float* __restrict__ sel) {
    int b = blockIdx.x;
    int t = ix[b];
    sel[b * HID + threadIdx.x] = of[(size_t)b * (SEQ * HID) + (size_t)t * HID + threadIdx.x];
}

// ---------------- launch ----------------
extern "C" void kernel_launch(void* const* d_in, const int* in_sizes, int n_in,
                              void* d_out, int out_size) {
    const float* img = (const float*)d_in[0];
    const float* phr = (const float*)d_in[1];
    const int*   six = (const int*)d_in[3];
    const float* Wc  = (const float*)d_in[4];
    const float* bc  = (const float*)d_in[5];
    const float* Wp  = (const float*)d_in[6];
    const float* bp  = (const float*)d_in[7];
    const float* Wih = (const float*)d_in[8];
    const float* bih = (const float*)d_in[9];
    const float* Whh = (const float*)d_in[10];
    const float* bhh = (const float*)d_in[11];
    const float* W1  = (const float*)d_in[12];
    const float* b1  = (const float*)d_in[13];
    const float* W2  = (const float*)d_in[14];
    const float* b2  = (const float*)d_in[15];

    float* out = (float*)d_out;
    float* lp  = out + OFF_LP;
    float* of  = out + OFF_OF;
    float* sel = out + OFF_SEL;

    emb_kernel <<<64, 64>>>(phr, Wp, bp);
    fuse_kernel<<<256, 256>>>(img, Wc, bc);
    lstm_kernel<<<128, 512>>>(Whh, Wih, bih, bhh, of);
    cls_kernel <<<256, 256>>>(of, W1, b1, W2, b2, lp);
    sel_kernel <<<64, 256>>>(six, of, sel);
}

// round 17
// speedup vs baseline: 1.0863x; 1.0863x over previous
#include <cuda_runtime.h>
#include <cstdint>
#include <math.h>

// Problem dims
#define NB   64
#define SEQ  512
#define IMG  3200
#define FC   64
#define HID  256
#define G4   1024

// Output layout (floats): [logprobs 64*512*2 | output_feats 64*512*256 | selected 64*256]
#define OFF_LP  0
#define OFF_OF  (NB*SEQ*2)
#define OFF_SEL (OFF_OF + NB*SEQ*HID)

// ---------------- scratch ----------------
__device__ float g_emb[NB * FC];
__device__ float g_fuse[NB * SEQ * FC];

// ---------------- helpers ----------------
__device__ __forceinline__ float2 ffma2(float2 a, float2 b, float2 c) {
    unsigned long long ua = *reinterpret_cast<unsigned long long*>(&a);
    unsigned long long ub = *reinterpret_cast<unsigned long long*>(&b);
    unsigned long long uc = *reinterpret_cast<unsigned long long*>(&c);
    unsigned long long ud;
    asm("fma.rn.f32x2 %0, %1, %2, %3;" : "=l"(ud) : "l"(ua), "l"(ub), "l"(uc));
    return *reinterpret_cast<float2*>(&ud);
}

__device__ __forceinline__ uint32_t smem_u32(const void* p) {
    uint32_t a;
    asm("{ .reg .u64 t; cvta.to.shared.u64 t, %1; cvt.u32.u64 %0, t; }" : "=r"(a) : "l"(p));
    return a;
}

// HW tanh (MUFU.TANH, sm_75+)
__device__ __forceinline__ float tanh_hw(float x) {
    float y;
    asm("tanh.approx.f32 %0, %1;" : "=f"(y) : "f"(x));
    return y;
}
__device__ __forceinline__ float sigm(float x)  { return fmaf(0.5f, tanh_hw(0.5f * x), 0.5f); }
__device__ __forceinline__ float tanh_(float x) { return tanh_hw(x); }

__device__ __forceinline__ void mbar_init(uint32_t a, uint32_t c) {
    asm volatile("mbarrier.init.shared.b64 [%0], %1;" :: "r"(a), "r"(c) : "memory");
}
__device__ __forceinline__ void mbar_expect_tx(uint32_t a, uint32_t tx) {
    asm volatile("mbarrier.arrive.expect_tx.shared.b64 _, [%0], %1;" :: "r"(a), "r"(tx) : "memory");
}
__device__ __forceinline__ void mbar_wait(uint32_t a, uint32_t phase) {
    asm volatile(
        "{\n\t"
        ".reg .pred P;\n\t"
        "WL_%=:\n\t"
        "mbarrier.try_wait.parity.acquire.cta.shared::cta.b64 P, [%0], %1, 0x989680;\n\t"
        "@P bra WD_%=;\n\t"
        "bra WL_%=;\n\t"
        "WD_%=:\n\t"
        "}" :: "r"(a), "r"(phase) : "memory");
}
__device__ __forceinline__ uint32_t mapa_u32(uint32_t a, uint32_t r) {
    uint32_t ra;
    asm("mapa.shared::cluster.u32 %0, %1, %2;" : "=r"(ra) : "r"(a), "r"(r));
    return ra;
}
__device__ __forceinline__ void st_async_f32(uint32_t dst, float v, uint32_t rbar) {
    asm volatile("st.async.shared::cluster.mbarrier::complete_tx::bytes.b32 [%0], %1, [%2];"
                 :: "r"(dst), "r"(__float_as_uint(v)), "r"(rbar) : "memory");
}

// tf32 helpers
__device__ __forceinline__ uint32_t f2tf32(float x) {
    uint32_t y;
    asm("cvt.rna.tf32.f32 %0, %1;" : "=r"(y) : "f"(x));
    return y;
}
__device__ __forceinline__ void mma_tf32(float c[4], uint32_t a0, uint32_t a1, uint32_t a2, uint32_t a3,
                                         uint32_t b0, uint32_t b1) {
    asm volatile("mma.sync.aligned.m16n8k8.row.col.f32.tf32.tf32.f32 "
                 "{%0,%1,%2,%3}, {%4,%5,%6,%7}, {%8,%9}, {%0,%1,%2,%3};"
                 : "+f"(c[0]), "+f"(c[1]), "+f"(c[2]), "+f"(c[3])
                 : "r"(a0), "r"(a1), "r"(a2), "r"(a3), "r"(b0), "r"(b1));
}

// ---------------- kernel 1: emb ----------------
__global__ void emb_kernel(const float* __restrict__ phr,
                           const float* __restrict__ Wp,
                           const float* __restrict__ bp) {
    __shared__ float ps[304];
    int b = blockIdx.x, tid = threadIdx.x;
    for (int i = tid; i < 300; i += 64) ps[i] = phr[b * 300 + i];
    __syncthreads();
    float acc = bp[tid];
#pragma unroll 4
    for (int k = 0; k < 300; k++) acc += ps[k] * Wp[k * 64 + tid];
    g_emb[b * 64 + tid] = fmaxf(acc, 0.0f);
}

// ---------------- kernel 2: fuse via 3xTF32 tensor-core mma ----------------
// relu(img @ W_cnn + b) * emb. Tile 128x64, 8 warps x (16 rows x 64 cols),
// K chunk 16 (2 k8 steps), double buffered. B converted to tf32 hi/lo at load.
#define PADA 136
#define PADB 72
__global__ __launch_bounds__(256) void fuse_kernel(const float* __restrict__ img,
                                                   const float* __restrict__ Wc,
                                                   const float* __restrict__ bc) {
    __shared__ float As[2][16][PADA];
    __shared__ float Bh[2][16][PADB];
    __shared__ float Bl[2][16][PADB];
    __shared__ float es[64];
    __shared__ float bcs[64];

    const int tid = threadIdx.x;
    const int w = tid >> 5, lane = tid & 31;
    const int row0 = blockIdx.x * 128;
    const int batch = row0 >> 9;

    if (tid < 64) { es[tid] = g_emb[batch * 64 + tid]; bcs[tid] = bc[tid]; }

    float c[8][4];
#pragma unroll
    for (int n = 0; n < 8; n++)
#pragma unroll
        for (int i = 0; i < 4; i++) c[n][i] = 0.0f;

    auto loadA = [&](int s, int kk) {
#pragma unroll
        for (int i = 0; i < 2; i++) {
            int id = tid * 2 + i;
            int m = id >> 2, q = id & 3;
            float4 v = *reinterpret_cast<const float4*>(img + (size_t)(row0 + m) * IMG + kk + q * 4);
            As[s][q * 4 + 0][m] = v.x;
            As[s][q * 4 + 1][m] = v.y;
            As[s][q * 4 + 2][m] = v.z;
            As[s][q * 4 + 3][m] = v.w;
        }
    };
    auto loadB = [&](int s, int kk) {
        int k = tid >> 4, cq = tid & 15;
        float4 v = *reinterpret_cast<const float4*>(Wc + (size_t)(kk + k) * 64 + cq * 4);
        float4 hi, lo;
        hi.x = __uint_as_float(f2tf32(v.x)); lo.x = v.x - hi.x;
        hi.y = __uint_as_float(f2tf32(v.y)); lo.y = v.y - hi.y;
        hi.z = __uint_as_float(f2tf32(v.z)); lo.z = v.z - hi.z;
        hi.w = __uint_as_float(f2tf32(v.w)); lo.w = v.w - hi.w;
        *reinterpret_cast<float4*>(&Bh[s][k][cq * 4]) = hi;
        *reinterpret_cast<float4*>(&Bl[s][k][cq * 4]) = lo;
    };

    loadA(0, 0);
    loadB(0, 0);
    __syncthreads();

    const int ar = w * 16 + (lane >> 2);   // A row (within 128)
    const int ak = lane & 3;               // A col base (within k8)
    const int bn = lane >> 2;              // B col (within n8)
    const int bk = lane & 3;               // B row base (within k8)

    for (int ch = 0; ch < 200; ch++) {
        int s = ch & 1;
        if (ch + 1 < 200) { loadA(s ^ 1, (ch + 1) * 16); loadB(s ^ 1, (ch + 1) * 16); }

#pragma unroll
        for (int kb = 0; kb < 16; kb += 8) {
            // ---- A fragment (m16 k8), hi/lo ----
            float a0 = As[s][kb + ak][ar];
            float a1 = As[s][kb + ak][ar + 8];
            float a2 = As[s][kb + ak + 4][ar];
            float a3 = As[s][kb + ak + 4][ar + 8];
            uint32_t ah0 = f2tf32(a0), ah1 = f2tf32(a1), ah2 = f2tf32(a2), ah3 = f2tf32(a3);
            uint32_t al0 = f2tf32(a0 - __uint_as_float(ah0));
            uint32_t al1 = f2tf32(a1 - __uint_as_float(ah1));
            uint32_t al2 = f2tf32(a2 - __uint_as_float(ah2));
            uint32_t al3 = f2tf32(a3 - __uint_as_float(ah3));

#pragma unroll
            for (int n = 0; n < 8; n++) {
                int col = n * 8 + bn;
                uint32_t bh0 = __float_as_uint(Bh[s][kb + bk][col]);
                uint32_t bh1 = __float_as_uint(Bh[s][kb + bk + 4][col]);
                uint32_t bl0 = __float_as_uint(Bl[s][kb + bk][col]);
                uint32_t bl1 = __float_as_uint(Bl[s][kb + bk + 4][col]);
                mma_tf32(c[n], ah0, ah1, ah2, ah3, bh0, bh1);
                mma_tf32(c[n], al0, al1, al2, al3, bh0, bh1);
                mma_tf32(c[n], ah0, ah1, ah2, ah3, bl0, bl1);
            }
        }
        __syncthreads();
    }

    // ---- epilogue: bias + relu + emb scale ----
#pragma unroll
    for (int n = 0; n < 8; n++) {
        int col0 = n * 8 + 2 * (lane & 3);
        float b0 = bcs[col0], b1 = bcs[col0 + 1];
        float e0 = es[col0],  e1 = es[col0 + 1];
        float2 r0, r1;
        r0.x = fmaxf(c[n][0] + b0, 0.f) * e0;
        r0.y = fmaxf(c[n][1] + b1, 0.f) * e1;
        r1.x = fmaxf(c[n][2] + b0, 0.f) * e0;
        r1.y = fmaxf(c[n][3] + b1, 0.f) * e1;
        *reinterpret_cast<float2*>(g_fuse + (size_t)(row0 + ar) * 64 + col0)     = r0;
        *reinterpret_cast<float2*>(g_fuse + (size_t)(row0 + ar + 8) * 64 + col0) = r1;
    }
}

// ---------------- kernel 3: LSTM (R15 exact) ----------------
#define PADQ 68
#define HBUF_BYTES (4 * 4 * PADQ * 4)   // one h buffer: 4352 B

__global__ void __cluster_dims__(8, 1, 1) __launch_bounds__(512, 1)
lstm_kernel(const float* __restrict__ Whh,
            const float* __restrict__ Wih,
            const float* __restrict__ bih,
            const float* __restrict__ bhh,
            float* __restrict__ of) {
    __shared__ __align__(16) float hbuf[2][4][4][PADQ];   // [buf][b][q][64(+4)]
    __shared__ __align__(16) float xs[2][4][PADQ];        // [buf][b][64(+4)]
    __shared__ __align__(16) float gsm[128][4];           // [gate-local][b]
    __shared__ __align__(16) float Wi_s[64 * 128];        // W_ih staging (init only)
    __shared__ __align__(8)  unsigned long long bars[2];

    const int tid  = threadIdx.x;
    const int warp = tid >> 5, lane = tid & 31;
    const int gl = lane & 7, q = lane >> 3;
    const int g  = warp * 8 + gl;          // gate slot 0..127
    const int rank   = blockIdx.x & 7;
    const int batch0 = (blockIdx.x >> 3) * 4;
    const int col = ((g >> 5) << 8) + (rank << 5) + (g & 31);  // column in [0,1024)

    // ---- stage W_ih slice coalesced (init only) ----
    for (int i = tid; i < 8192; i += 512) {
        int k = i >> 7, c = i & 127;
        int cg = ((c >> 5) << 8) + (rank << 5) + (c & 31);
        Wi_s[k * 128 + c] = Wih[(size_t)k * G4 + cg];
    }

    // ---- W_hh registers: k in [q*64, q*64+64), packed as 32 float2 ----
    float2 Wr[32];
    {
        const float* wp = Whh + (size_t)(q * 64) * G4 + col;
#pragma unroll
        for (int j = 0; j < 32; j++) {
            Wr[j].x = wp[(size_t)(2 * j) * G4];
            Wr[j].y = wp[(size_t)(2 * j + 1) * G4];
        }
    }
    // bias folded into xacc, added once (q==0 lanes only)
    float bg = (q == 0) ? (bih[col] + bhh[col]) : 0.0f;

    const uint32_t bar0 = smem_u32(&bars[0]);
    if (tid == 0) {
        mbar_init(bar0, 1);
        mbar_init(bar0 + 8, 1);
        mbar_expect_tx(bar0, 4096);       // armed for first use (t=2)
        mbar_expect_tx(bar0 + 8, 4096);   // armed for first use (t=1)
    }
    // prefetch x for t=0 (xs[0]) and t=1 (xs[1])
    if (tid < 128) {
        int buf = tid >> 6;               // 0 or 1
        int e = tid & 63;
        int b = e >> 4, j = e & 15;
        *reinterpret_cast<float4*>(&xs[buf][b][j * 4]) =
            *reinterpret_cast<const float4*>(g_fuse + ((size_t)(batch0 + b) * SEQ + buf) * FC + j * 4);
    }
    __syncthreads();

    // ---- W_ih registers: k in [q*16, q*16+16) for gate g ----
    float2 Wir[8];
#pragma unroll
    for (int j = 0; j < 8; j++) {
        int k = q * 16 + 2 * j;
        Wir[j].x = Wi_s[k * 128 + g];
        Wir[j].y = Wi_s[(k + 1) * 128 + g];
    }

    asm volatile("barrier.cluster.arrive.aligned;" ::: "memory");
    asm volatile("barrier.cluster.wait.aligned;"   ::: "memory");

    // producer identity (threads 0..127): batch bb, unit ub
    const int bb = tid >> 5, ub = tid & 31;
    const int kglob = (rank << 5) + ub;
    uint32_t dst_loc0 = 0, barloc = bar0;
    if (tid < 128)
        dst_loc0 = smem_u32(&hbuf[0][bb][kglob >> 6][kglob & 63]);

    // ---- xacc for t=0 (from xs[0]) ----
    float xacc[4];
    {
#pragma unroll
        for (int b = 0; b < 4; b++) {
            const float* xp = &xs[0][b][q * 16];
            float2 a = make_float2(bg * 0.5f, bg * 0.5f);   // a.x + a.y = bg
#pragma unroll
            for (int i = 0; i < 8; i++) {
                float2 x2 = *reinterpret_cast<const float2*>(xp + 2 * i);
                a = ffma2(Wir[i], x2, a);
            }
            xacc[b] = a.x + a.y;
        }
    }

    float creg = 0.0f;
    int ph0 = 0, ph1 = 0;

    for (int t = 0; t < SEQ; t++) {
        const int p = t & 1;
        float val[4];
#pragma unroll
        for (int b = 0; b < 4; b++) val[b] = xacc[b];

        if (t > 0) {
            uint32_t barp = bar0 + p * 8;
            int par = p ? ph1 : ph0;
            mbar_wait(barp, par);
            if (p) ph1 ^= 1; else ph0 ^= 1;
            if (tid == 0) mbar_expect_tx(barp, 4096);   // re-arm for t+2

            // ---- recurrent GEMM ----
#pragma unroll
            for (int b = 0; b < 4; b++) {
                float2 acc = make_float2(0.f, 0.f);
                const float* hp = &hbuf[p][b][q][0];
#pragma unroll
                for (int j = 0; j < 16; j++) {
                    float4 h4 = *reinterpret_cast<const float4*>(hp + j * 4);
                    acc = ffma2(Wr[2 * j],     make_float2(h4.x, h4.y), acc);
                    acc = ffma2(Wr[2 * j + 1], make_float2(h4.z, h4.w), acc);
                }
                val[b] += acc.x + acc.y;
            }
        }

        // reduce across quarters
#pragma unroll
        for (int b = 0; b < 4; b++) {
            val[b] += __shfl_xor_sync(0xffffffffu, val[b], 8);
            val[b] += __shfl_xor_sync(0xffffffffu, val[b], 16);
        }
        if (lane < 8) {
            float4 v = make_float4(val[0], val[1], val[2], val[3]);
            *reinterpret_cast<float4*>(&gsm[warp * 8 + lane][0]) = v;
        }
        __syncthreads();

        if (tid < 128) {
            float gi = gsm[ub][bb];
            float gf = gsm[32 + ub][bb];
            float gg = gsm[64 + ub][bb];
            float go = gsm[96 + ub][bb];
            float tg = tanh_(gg);
            creg = sigm(gf) * creg + sigm(gi) * tg;
            float h = sigm(go) * tanh_(creg);

            if (t + 1 < SEQ) {
                uint32_t doff = dst_loc0 + (p ^ 1) * HBUF_BYTES;
                uint32_t boff = barloc + (p ^ 1) * 8;
#pragma unroll
                for (int r = 0; r < 8; r++) {
                    uint32_t rd = mapa_u32(doff, r);
                    uint32_t rb = mapa_u32(boff, r);
                    st_async_f32(rd, h, rb);
                }
            }
            of[(size_t)(batch0 + bb) * (SEQ * HID) + (size_t)t * HID + (rank << 5) + ub] = h;
        } else if (tid < 192 && t + 2 < SEQ) {
            // prefetch x for t+2 into xs[(t+2)&1] = xs[p]
            int e = tid - 128;
            int b = e >> 4, j = e & 15;
            *reinterpret_cast<float4*>(&xs[p][b][j * 4]) =
                *reinterpret_cast<const float4*>(g_fuse + ((size_t)(batch0 + b) * SEQ + (t + 2)) * FC + j * 4);
        }

        // ---- xacc for t+1 from xs[p^1] ----
        if (t + 1 < SEQ) {
#pragma unroll
            for (int b = 0; b < 4; b++) {
                const float* xp = &xs[p ^ 1][b][q * 16];
                float2 a = make_float2(bg * 0.5f, bg * 0.5f);
#pragma unroll
                for (int i = 0; i < 8; i++) {
                    float2 x2 = *reinterpret_cast<const float2*>(xp + 2 * i);
                    a = ffma2(Wir[i], x2, a);
                }
                xacc[b] = a.x + a.y;
            }
        }
        // no trailing sync
    }

    asm volatile("barrier.cluster.arrive.aligned;" ::: "memory");
    asm volatile("barrier.cluster.wait.aligned;"   ::: "memory");
}

// ---------------- kernel 4: classifier + log_softmax ----------------
__global__ __launch_bounds__(256) void cls_kernel(const float* __restrict__ of,
                                                  const float* __restrict__ W1,
                                                  const float* __restrict__ b1,
                                                  const float* __restrict__ W2,
                                                  const float* __restrict__ b2,
                                                  float* __restrict__ lp) {
    __shared__ float As[2][16][132];
    __shared__ float Bs[2][16][64];

    const int tid = threadIdx.x;
    const int tx = tid & 15, ty = tid >> 4;
    const int row0 = blockIdx.x * 128;

    float b1r[4], w20[4], w21[4];
#pragma unroll
    for (int c = 0; c < 4; c++) {
        int f = tx * 4 + c;
        b1r[c] = b1[f];
        w20[c] = W2[f * 2 + 0];
        w21[c] = W2[f * 2 + 1];
    }
    const float bb0 = b2[0], bb1 = b2[1];

    float2 acc[4][4];
#pragma unroll
    for (int mp = 0; mp < 4; mp++)
#pragma unroll
        for (int c = 0; c < 4; c++) acc[mp][c] = make_float2(0.f, 0.f);

    auto loadA = [&](int s, int kk) {
#pragma unroll
        for (int i = 0; i < 2; i++) {
            int id = tid * 2 + i;
            int m = id >> 2, q = id & 3;
            float4 v = *reinterpret_cast<const float4*>(of + (size_t)(row0 + m) * HID + kk + q * 4);
            As[s][q * 4 + 0][m] = v.x;
            As[s][q * 4 + 1][m] = v.y;
            As[s][q * 4 + 2][m] = v.z;
            As[s][q * 4 + 3][m] = v.w;
        }
    };
    auto loadB = [&](int s, int kk) {
        int k = tid >> 4, q = tid & 15;
        *reinterpret_cast<float4*>(&Bs[s][k][q * 4]) =
            *reinterpret_cast<const float4*>(W1 + (size_t)(kk + k) * 64 + q * 4);
    };

    loadA(0, 0);
    loadB(0, 0);
    __syncthreads();

    for (int ch = 0; ch < 16; ch++) {
        int s = ch & 1;
        if (ch + 1 < 16) { loadA(s ^ 1, (ch + 1) * 16); loadB(s ^ 1, (ch + 1) * 16); }
#pragma unroll
        for (int k = 0; k < 16; k++) {
            float4 b4 = *reinterpret_cast<const float4*>(&Bs[s][k][tx * 4]);
            float4 a0 = *reinterpret_cast<const float4*>(&As[s][k][ty * 8]);
            float4 a1 = *reinterpret_cast<const float4*>(&As[s][k][ty * 8 + 4]);
            float2 aa[4] = { {a0.x, a0.y}, {a0.z, a0.w}, {a1.x, a1.y}, {a1.z, a1.w} };
            float  bb[4] = { b4.x, b4.y, b4.z, b4.w };
#pragma unroll
            for (int c = 0; c < 4; c++) {
                float2 bv = make_float2(bb[c], bb[c]);
#pragma unroll
                for (int mp = 0; mp < 4; mp++) acc[mp][c] = ffma2(aa[mp], bv, acc[mp][c]);
            }
        }
        __syncthreads();
    }

#pragma unroll
    for (int mp = 0; mp < 4; mp++) {
#pragma unroll
        for (int half = 0; half < 2; half++) {
            float p0 = 0.f, p1 = 0.f;
#pragma unroll
            for (int c = 0; c < 4; c++) {
                float vv = half ? acc[mp][c].y : acc[mp][c].x;
                float hd = fmaxf(vv + b1r[c], 0.f);
                p0 += hd * w20[c];
                p1 += hd * w21[c];
            }
#pragma unroll
            for (int s = 1; s < 16; s <<= 1) {
                p0 += __shfl_xor_sync(0xffffffffu, p0, s);
                p1 += __shfl_xor_sync(0xffffffffu, p1, s);
            }
            if ((tid & 15) == 0) {
                float l0 = p0 + bb0, l1 = p1 + bb1;
                float m = fmaxf(l0, l1);
                float lse = m + logf(expf(l0 - m) + expf(l1 - m));
                int row = row0 + ty * 8 + mp * 2 + half;
                lp[row * 2 + 0] = l0 - lse;
                lp[row * 2 + 1] = l1 - lse;
            }
        }
    }
}

// ---------------- kernel 5: gather selected ----------------
__global__ void sel_kernel(const int* __restrict__ ix, const float* __restrict__ of,
                           float* __restrict__ sel) {
    int b = blockIdx.x;
    int t = ix[b];
    sel[b * HID + threadIdx.x] = of[(size_t)b * (SEQ * HID) + (size_t)t * HID + threadIdx.x];
}

// ---------------- launch ----------------
extern "C" void kernel_launch(void* const* d_in, const int* in_sizes, int n_in,
                              void* d_out, int out_size) {
    const float* img = (const float*)d_in[0];
    const float* phr = (const float*)d_in[1];
    const int*   six = (const int*)d_in[3];
    const float* Wc  = (const float*)d_in[4];
    const float* bc  = (const float*)d_in[5];
    const float* Wp  = (const float*)d_in[6];
    const float* bp  = (const float*)d_in[7];
    const float* Wih = (const float*)d_in[8];
    const float* bih = (const float*)d_in[9];
    const float* Whh = (const float*)d_in[10];
    const float* bhh = (const float*)d_in[11];
    const float* W1  = (const float*)d_in[12];
    const float* b1  = (const float*)d_in[13];
    const float* W2  = (const float*)d_in[14];
    const float* b2  = (const float*)d_in[15];

    float* out = (float*)d_out;
    float* lp  = out + OFF_LP;
    float* of  = out + OFF_OF;
    float* sel = out + OFF_SEL;

    emb_kernel <<<64, 64>>>(phr, Wp, bp);
    fuse_kernel<<<256, 256>>>(img, Wc, bc);
    lstm_kernel<<<128, 512>>>(Whh, Wih, bih, bhh, of);
    cls_kernel <<<256, 256>>>(of, W1, b1, W2, b2, lp);
    sel_kernel <<<64, 256>>>(six, of, sel);
}